// round 13
// baseline (speedup 1.0000x reference)
#include <cuda_runtime.h>
#include <cuda_fp16.h>
#include <cstdint>
#include <math.h>

// ---------------- problem constants ----------------
#define NS   5760
#define CO   640
#define KD   192
#define B_   8
#define WAY_ 5
#define NQ_  75
#define P_   9
#define NTOT (NS * 16)       // 92160
#define KE2  576             // 3 * 192 fp16-split K
#define TNB  32              // N per block = 2 images
#define KC   16              // K halves per chunk
#define NCH  36              // 576 / 16

// ---------------- device scratch ----------------
__device__ __align__(128) __half g_W[(size_t)CO * KE2];    // 737 KB
__device__ float g_u[(size_t)NS * CO];

__device__ __forceinline__ uint32_t smem_u32(const void* p) {
    uint32_t a;
    asm("{ .reg .u64 t; cvta.to.shared.u64 t, %1; cvt.u32.u64 %0, t; }"
        : "=r"(a) : "l"(p));
    return a;
}

// ---------------------------------------------------------------------------
// Prep W: fp16 split, K-concat [w0 | w0 | w1]
// ---------------------------------------------------------------------------
__global__ void k_prepw(const float* __restrict__ w) {
    int i = blockIdx.x * 256 + threadIdx.x;
    if (i >= CO * KD) return;
    int ch = i / KD, k = i % KD;
    float v = w[i];
    __half h0 = __float2half_rn(v);
    __half h1 = __float2half_rn(v - __half2float(h0));
    size_t b = (size_t)ch * KE2;
    g_W[b + k]       = h0;
    g_W[b + 192 + k] = h0;
    g_W[b + 384 + k] = h1;
}

// ---------------------------------------------------------------------------
// Fused im2col + GEMM + norms — 2 CTAs/SM edition.
// 320 threads (10 warps), warp owns M=64 rows, TNB=32 (2 images).
// Per-warp triple-buffered A (swizzled 2048B bufs), 36 chunks of KC=16.
// ---------------------------------------------------------------------------
#define BST      584                      // B row stride (halves): 1168 B
#define OFF_B    0
#define BSZ      (TNB * BST * 2)          // 37376
#define OFF_A    BSZ
#define ABUF_SZ  2048                     // 64 rows x 32 B, swizzled, no pad
#define AWARP_SZ (3 * ABUF_SZ)            // 6144 per warp
#define SMT      (OFF_A + 10 * AWARP_SZ)  // 98816  (x2 = 197632 <= 227KB)
#define OFF_SSQ  OFF_A
#define OFF_SS2  (OFF_A + 128)
#define OFF_VSM  (OFF_A + 144)

#define LDSM4(r0, r1, r2, r3, ad) \
    asm volatile("ldmatrix.sync.aligned.m8n8.x4.shared.b16 {%0,%1,%2,%3},[%4];" \
                 : "=r"(r0), "=r"(r1), "=r"(r2), "=r"(r3) : "r"(ad))

__global__ void __launch_bounds__(320, 2) k_gemm(const float* __restrict__ data) {
    extern __shared__ char sm[];
    const int t = threadIdx.x, w = t >> 5, lane = t & 31;
    const int bid = blockIdx.x;
    const uint32_t sb = smem_u32(sm);
    const uint32_t aWarpBase = sb + OFF_A + w * AWARP_SZ;

    // --- per-warp A chunk: 64 rows x 32 B (KC=16), swizzled, 4x16B per lane ---
    auto issueA = [&](int c, int buf) {
        const int kc = KC * c;
#pragma unroll
        for (int i = 0; i < 4; i++) {
            int g = lane + 32 * i;
            int row = g >> 1, part = g & 1;
            const __half* src = g_W + (size_t)(w * 64 + row) * KE2 + kc + part * 8;
            uint32_t dst = aWarpBase + buf * ABUF_SZ + row * 32 +
                           ((part ^ ((row >> 2) & 1)) << 4);
            asm volatile("cp.async.cg.shared.global [%0], [%1], 16;"
                         :: "r"(dst), "l"(src));
        }
        asm volatile("cp.async.commit_group;");
    };
    issueA(0, 0);
    issueA(1, 1);

    // --- stage B: im2col + fp16 split, 8 pixels -> 3 x 16B stores ---
    const float* imgs = data + (size_t)bid * 2 * 3072;
    for (int g = t; g < 768; g += 320) {
        int j = g / 384, rem = g - j * 384;
        int base = rem * 8;
        int ci = base >> 10, r2 = base & 1023;
        int row = r2 >> 5, cb = r2 & 31;
        int kb  = ci * 64 + (row & 7) * 8;
        int pos = (row >> 3) * 4 + (cb >> 3);
        const float* p = imgs + j * 3072 + base;
        float4 va = *reinterpret_cast<const float4*>(p);
        float4 vb = *reinterpret_cast<const float4*>(p + 4);
        float vv[8] = {va.x, va.y, va.z, va.w, vb.x, vb.y, vb.z, vb.w};
        union { __half2 h2[4]; uint4 u; } t0, t1;
#pragma unroll
        for (int i = 0; i < 4; i++) {
            __half a0 = __float2half_rn(vv[2 * i]);
            __half b0 = __float2half_rn(vv[2 * i + 1]);
            __half a1 = __float2half_rn(vv[2 * i]     - __half2float(a0));
            __half b1 = __float2half_rn(vv[2 * i + 1] - __half2float(b0));
            t0.h2[i] = __halves2half2(a0, b0);
            t1.h2[i] = __halves2half2(a1, b1);
        }
        char* rb = sm + OFF_B + (j * 16 + pos) * (BST * 2);
        *reinterpret_cast<uint4*>(rb + 2 * kb)         = t0.u;
        *reinterpret_cast<uint4*>(rb + 2 * (192 + kb)) = t1.u;
        *reinterpret_cast<uint4*>(rb + 2 * (384 + kb)) = t0.u;
    }
    __syncthreads();   // ONLY block-wide sync before epilogue

    float acc[4][4][4];
#pragma unroll
    for (int mt = 0; mt < 4; mt++)
#pragma unroll
        for (int nt = 0; nt < 4; nt++)
#pragma unroll
            for (int c = 0; c < 4; c++) acc[mt][nt][c] = 0.f;

    const int lm = lane >> 3;
    const int arow = (lm & 1) * 8 + (lane & 7);
    const uint32_t aAddr = aWarpBase + arow * 32 +
                           (((lm >> 1) ^ ((arow >> 2) & 1)) << 4);
    const uint32_t bAddr = sb + OFF_B +
        (((lm >> 1) * 8 + (lane & 7)) * BST + (lm & 1) * 8) * 2;

    for (int c = 0; c < NCH; c++) {
        if (c + 1 < NCH) asm volatile("cp.async.wait_group 1;");
        else             asm volatile("cp.async.wait_group 0;");
        __syncwarp();
        if (c + 2 < NCH) issueA(c + 2, (c + 2) % 3);

        const uint32_t aBuf = aAddr + (c % 3) * ABUF_SZ;
        uint32_t a[4][4];
#pragma unroll
        for (int mt = 0; mt < 4; mt++)
            LDSM4(a[mt][0], a[mt][1], a[mt][2], a[mt][3], aBuf + mt * 512);
#pragma unroll
        for (int ntp = 0; ntp < 2; ntp++) {
            uint32_t b[4];
            LDSM4(b[0], b[1], b[2], b[3],
                  bAddr + ntp * (16 * BST * 2) + c * (KC * 2));
#pragma unroll
            for (int sub = 0; sub < 2; sub++) {
                int nt = 2 * ntp + sub;
#pragma unroll
                for (int mt = 0; mt < 4; mt++) {
                    asm volatile(
                        "mma.sync.aligned.m16n8k16.row.col.f32.f16.f16.f32 "
                        "{%0,%1,%2,%3},{%4,%5,%6,%7},{%8,%9},{%0,%1,%2,%3};"
                        : "+f"(acc[mt][nt][0]), "+f"(acc[mt][nt][1]),
                          "+f"(acc[mt][nt][2]), "+f"(acc[mt][nt][3])
                        : "r"(a[mt][0]), "r"(a[mt][1]), "r"(a[mt][2]), "r"(a[mt][3]),
                          "r"(b[2 * sub]), "r"(b[2 * sub + 1]));
                }
            }
        }
    }
    __syncthreads();   // all warps done; A region reusable as scratch

    float* ssq = reinterpret_cast<float*>(sm + OFF_SSQ);
    float* ss2 = reinterpret_cast<float*>(sm + OFF_SS2);
    float* vsm = reinterpret_cast<float*>(sm + OFF_VSM);
    if (t < 32) ssq[t] = 0.f;
    if (t >= 32 && t < 34) ss2[t - 32] = 0.f;
    __syncthreads();

    // ---- epilogue: per-position (col) channel L2-norm ----
    {
        float cs[8];
#pragma unroll
        for (int nt = 0; nt < 4; nt++)
#pragma unroll
            for (int par = 0; par < 2; par++) {
                float s = 0.f;
#pragma unroll
                for (int mt = 0; mt < 4; mt++) {
                    float x0 = acc[mt][nt][par], x1 = acc[mt][nt][2 + par];
                    s = fmaf(x0, x0, s);
                    s = fmaf(x1, x1, s);
                }
                cs[nt * 2 + par] = s;
            }
#pragma unroll
        for (int i = 0; i < 8; i++) {
            cs[i] += __shfl_xor_sync(0xffffffffu, cs[i], 4);
            cs[i] += __shfl_xor_sync(0xffffffffu, cs[i], 8);
            cs[i] += __shfl_xor_sync(0xffffffffu, cs[i], 16);
        }
        if (lane < 4) {
#pragma unroll
            for (int nt = 0; nt < 4; nt++)
#pragma unroll
                for (int par = 0; par < 2; par++)
                    atomicAdd(&ssq[nt * 8 + lane * 2 + par], cs[nt * 2 + par]);
        }
    }
    __syncthreads();
    if (t < 32) ssq[t] = 1.f / fmaxf(sqrtf(ssq[t]), 1e-12f);
    __syncthreads();

    // ---- pool over positions + final channel L2-norm (2 images) ----
    float sq[2] = {0.f, 0.f};
#pragma unroll
    for (int mt = 0; mt < 4; mt++)
#pragma unroll
        for (int h = 0; h < 2; h++)
#pragma unroll
            for (int j = 0; j < 2; j++) {
                float s = 0.f;
#pragma unroll
                for (int ntl = 0; ntl < 2; ntl++) {
                    int nt = 2 * j + ntl;
#pragma unroll
                    for (int par = 0; par < 2; par++) {
                        int col = nt * 8 + (lane & 3) * 2 + par;
                        s = fmaf(acc[mt][nt][h * 2 + par], ssq[col], s);
                    }
                }
                s += __shfl_xor_sync(0xffffffffu, s, 1);
                s += __shfl_xor_sync(0xffffffffu, s, 2);
                if ((lane & 3) == 0) {
                    int row = w * 64 + mt * 16 + h * 8 + (lane >> 2);
                    float v = s * 0.0625f;
                    vsm[row * 2 + j] = v;
                    sq[j] = fmaf(v, v, sq[j]);
                }
            }
#pragma unroll
    for (int j = 0; j < 2; j++) {
        sq[j] += __shfl_xor_sync(0xffffffffu, sq[j], 4);
        sq[j] += __shfl_xor_sync(0xffffffffu, sq[j], 8);
        sq[j] += __shfl_xor_sync(0xffffffffu, sq[j], 16);
    }
    if (lane == 0) {
        atomicAdd(&ss2[0], sq[0]);
        atomicAdd(&ss2[1], sq[1]);
    }
    __syncthreads();
    if (t < 2) ss2[t] = 1.f / fmaxf(sqrtf(ss2[t]), 1e-12f);
    __syncthreads();

    for (int g = t; g < 1280; g += 320) {
        int ch = g >> 1, j = g & 1;
        g_u[(size_t)(2 * bid + j) * CO + ch] = vsm[ch * 2 + j] * ss2[j];
    }
}

// ---------------------------------------------------------------------------
// Sim + greedy, single-pass (R12, passing): block per (b,n), 384 threads.
// ---------------------------------------------------------------------------
#define QS 644
#define SIMSMT ((54 * QS + 360 * 9 + 5 * 81) * 4)

__global__ void __launch_bounds__(384) k_sim(float* __restrict__ out) {
    extern __shared__ float smf[];
    float* rows = smf;                    // [54][QS]: 0..8 query, 9..53 support
    float* psum = smf + 54 * QS;          // [360][9]
    float* simm = psum + 360 * 9;         // [5][81]

    const int b = blockIdx.x / NQ_;
    const int n = blockIdx.x % NQ_;
    const int t = threadIdx.x;

    const float* qb = g_u + ((size_t)(b * 80 + WAY_ + n) * P_) * CO;
    const float* sb = g_u + ((size_t)(b * 80) * P_) * CO;
    for (int i = t; i < 54 * 160; i += 384) {
        int r = i / 160, c4 = (i % 160) * 4;
        const float* src = (r < 9) ? qb + (size_t)r * CO + c4
                                   : sb + (size_t)(r - 9) * CO + c4;
        *reinterpret_cast<float4*>(&rows[r * QS + c4]) =
            *reinterpret_cast<const float4*>(src);
    }
    __syncthreads();

    if (t < 360) {
        const int m = t / 72, r = t % 72;
        const int tt = r >> 3, ss = r & 7;
        const int k0 = ss * 80;
        const float* s0 = &rows[(9 + m * 9 + (tt / 3) * 3 + 0) * QS + k0];
        const float* s1 = s0 + QS;
        const float* s2 = s1 + QS;
        const float* q0 = &rows[((tt % 3) * 3 + 0) * QS + k0];
        const float* q1 = q0 + QS;
        const float* q2 = q1 + QS;
        float a00 = 0.f, a01 = 0.f, a02 = 0.f;
        float a10 = 0.f, a11 = 0.f, a12 = 0.f;
        float a20 = 0.f, a21 = 0.f, a22 = 0.f;
#pragma unroll 2
        for (int k = 0; k < 80; k += 4) {
            float4 sv0 = *reinterpret_cast<const float4*>(s0 + k);
            float4 sv1 = *reinterpret_cast<const float4*>(s1 + k);
            float4 sv2 = *reinterpret_cast<const float4*>(s2 + k);
            float4 qv0 = *reinterpret_cast<const float4*>(q0 + k);
            float4 qv1 = *reinterpret_cast<const float4*>(q1 + k);
            float4 qv2 = *reinterpret_cast<const float4*>(q2 + k);
            a00 = fmaf(sv0.x, qv0.x, a00); a00 = fmaf(sv0.y, qv0.y, a00);
            a00 = fmaf(sv0.z, qv0.z, a00); a00 = fmaf(sv0.w, qv0.w, a00);
            a01 = fmaf(sv0.x, qv1.x, a01); a01 = fmaf(sv0.y, qv1.y, a01);
            a01 = fmaf(sv0.z, qv1.z, a01); a01 = fmaf(sv0.w, qv1.w, a01);
            a02 = fmaf(sv0.x, qv2.x, a02); a02 = fmaf(sv0.y, qv2.y, a02);
            a02 = fmaf(sv0.z, qv2.z, a02); a02 = fmaf(sv0.w, qv2.w, a02);
            a10 = fmaf(sv1.x, qv0.x, a10); a10 = fmaf(sv1.y, qv0.y, a10);
            a10 = fmaf(sv1.z, qv0.z, a10); a10 = fmaf(sv1.w, qv0.w, a10);
            a11 = fmaf(sv1.x, qv1.x, a11); a11 = fmaf(sv1.y, qv1.y, a11);
            a11 = fmaf(sv1.z, qv1.z, a11); a11 = fmaf(sv1.w, qv1.w, a11);
            a12 = fmaf(sv1.x, qv2.x, a12); a12 = fmaf(sv1.y, qv2.y, a12);
            a12 = fmaf(sv1.z, qv2.z, a12); a12 = fmaf(sv1.w, qv2.w, a12);
            a20 = fmaf(sv2.x, qv0.x, a20); a20 = fmaf(sv2.y, qv0.y, a20);
            a20 = fmaf(sv2.z, qv0.z, a20); a20 = fmaf(sv2.w, qv0.w, a20);
            a21 = fmaf(sv2.x, qv1.x, a21); a21 = fmaf(sv2.y, qv1.y, a21);
            a21 = fmaf(sv2.z, qv1.z, a21); a21 = fmaf(sv2.w, qv1.w, a21);
            a22 = fmaf(sv2.x, qv2.x, a22); a22 = fmaf(sv2.y, qv2.y, a22);
            a22 = fmaf(sv2.z, qv2.z, a22); a22 = fmaf(sv2.w, qv2.w, a22);
        }
        float* pr = &psum[t * 9];
        pr[0] = a00; pr[1] = a01; pr[2] = a02;
        pr[3] = a10; pr[4] = a11; pr[5] = a12;
        pr[6] = a20; pr[7] = a21; pr[8] = a22;
    }
    __syncthreads();

    for (int i = t; i < 405; i += 384) {
        int m = i / 81, e = i % 81;
        int h = e / 9, wq = e % 9;
        int tile = (h / 3) * 3 + wq / 3;
        int el = (h % 3) * 3 + (wq % 3);
        float s = 0.f;
#pragma unroll
        for (int ss = 0; ss < 8; ss++)
            s += psum[(m * 72 + tile * 8 + ss) * 9 + el];
        simm[m * 81 + e] = s;
    }
    __syncthreads();

    const int wp = t >> 5, lane = t & 31;
    if (wp < WAY_) {
        const float* sv = &simm[wp * 81];
        float v0 = sv[lane];
        float v1 = sv[lane + 32];
        float v2 = (lane + 64 < 81) ? sv[lane + 64] : -1e30f;
        unsigned rmask = 0x1FFu, cmask = 0x1FFu;
        float totalv = 0.f, beta = 1.f;
        for (int it = 0; it < 9; it++) {
            float bv = -1e30f;
            int bidx = 999;
            int j = lane;
            if (((rmask >> (j / 9)) & 1) && ((cmask >> (j % 9)) & 1)) {
                bv = v0; bidx = j;
            }
            j = lane + 32;
            if (((rmask >> (j / 9)) & 1) && ((cmask >> (j % 9)) & 1)) {
                if (v1 > bv || (v1 == bv && j < bidx)) { bv = v1; bidx = j; }
            }
            j = lane + 64;
            if (j < 81 && ((rmask >> (j / 9)) & 1) && ((cmask >> (j % 9)) & 1)) {
                if (v2 > bv || (v2 == bv && j < bidx)) { bv = v2; bidx = j; }
            }
#pragma unroll
            for (int off = 16; off; off >>= 1) {
                float ov = __shfl_xor_sync(0xffffffffu, bv, off);
                int   oi = __shfl_xor_sync(0xffffffffu, bidx, off);
                if (ov > bv || (ov == bv && oi < bidx)) { bv = ov; bidx = oi; }
            }
            totalv = fmaf(fmaxf(bv, 0.f), beta, totalv);
            beta *= 0.5f;
            rmask &= ~(1u << (bidx / 9));
            cmask &= ~(1u << (bidx % 9));
        }
        if (lane == 0) out[((size_t)b * NQ_ + n) * WAY_ + wp] = totalv;
    }
}

// ---------------------------------------------------------------------------
extern "C" void kernel_launch(void* const* d_in, const int* in_sizes, int n_in,
                              void* d_out, int out_size) {
    const float* data   = (const float*)d_in[0];
    const float* conv_w = (const float*)d_in[1];
    (void)in_sizes; (void)n_in; (void)out_size;

    static bool attr_set = false;
    if (!attr_set) {
        cudaFuncSetAttribute(k_gemm, cudaFuncAttributeMaxDynamicSharedMemorySize, SMT);
        cudaFuncSetAttribute(k_sim, cudaFuncAttributeMaxDynamicSharedMemorySize, SIMSMT);
        attr_set = true;
    }

    k_prepw<<<(CO * KD + 255) / 256, 256>>>(conv_w);
    k_gemm<<<NTOT / TNB, 320, SMT>>>(data);
    k_sim<<<B_ * NQ_, 384, SIMSMT>>>((float*)d_out);
}

// round 14
// speedup vs baseline: 1.0757x; 1.0757x over previous
#include <cuda_runtime.h>
#include <cuda_fp16.h>
#include <cstdint>
#include <math.h>

// ---------------- problem constants ----------------
#define NS   5760
#define CO   640
#define KD   192
#define B_   8
#define WAY_ 5
#define NQ_  75
#define P_   9
#define NTOT (NS * 16)       // 92160
#define KE2  576             // 3 * 192 fp16-split K
#define TNB  64              // N per block = 4 images
#define KC   32              // K halves per chunk
#define NCH  18              // 576 / 32

// ---------------- device scratch ----------------
__device__ __align__(128) __half g_W[(size_t)CO * KE2];    // 737 KB
__device__ float g_u[(size_t)NS * CO];

__device__ __forceinline__ uint32_t smem_u32(const void* p) {
    uint32_t a;
    asm("{ .reg .u64 t; cvta.to.shared.u64 t, %1; cvt.u32.u64 %0, t; }"
        : "=r"(a) : "l"(p));
    return a;
}

// ---------------------------------------------------------------------------
// Prep W: fp16 split, K-concat [w0 | w0 | w1]
// ---------------------------------------------------------------------------
__global__ void k_prepw(const float* __restrict__ w) {
    int i = blockIdx.x * 256 + threadIdx.x;
    if (i >= CO * KD) return;
    int ch = i / KD, k = i % KD;
    float v = w[i];
    __half h0 = __float2half_rn(v);
    __half h1 = __float2half_rn(v - __half2float(h0));
    size_t b = (size_t)ch * KE2;
    g_W[b + k]       = h0;
    g_W[b + 192 + k] = h0;
    g_W[b + 384 + k] = h1;
}

// ---------------------------------------------------------------------------
// Fused im2col + GEMM + norms (R12 config: 640 thr, TNB=64, per-warp
// triple-buffered A, one block sync). + unroll-3 mainloop.
// ---------------------------------------------------------------------------
#define BST      584                      // B row stride (halves): 1168 B
#define AST      40                       // A row stride (halves): 80 B
#define OFF_B    0
#define BSZ      (TNB * BST * 2)          // 74752
#define OFF_A    BSZ
#define ABUF_SZ  (32 * AST * 2)           // 2560 per warp-buffer
#define AWARP_SZ (3 * ABUF_SZ)            // 7680 per warp
#define SMT      (OFF_A + 20 * AWARP_SZ)  // 228352
#define OFF_SSQ  OFF_A
#define OFF_SS2  (OFF_A + 256)
#define OFF_VSM  (OFF_A + 272)

#define LDSM4(r0, r1, r2, r3, ad) \
    asm volatile("ldmatrix.sync.aligned.m8n8.x4.shared.b16 {%0,%1,%2,%3},[%4];" \
                 : "=r"(r0), "=r"(r1), "=r"(r2), "=r"(r3) : "r"(ad))

__global__ void __launch_bounds__(640, 1) k_gemm(const float* __restrict__ data) {
    extern __shared__ char sm[];
    const int t = threadIdx.x, w = t >> 5, lane = t & 31;
    const int bid = blockIdx.x;
    const uint32_t sb = smem_u32(sm);
    const uint32_t aWarpBase = sb + OFF_A + w * AWARP_SZ;

    auto issueA = [&](int c, int buf) {
        const int kc = KC * c;
#pragma unroll
        for (int i = 0; i < 4; i++) {
            int g = lane + 32 * i;
            int row = g >> 2, part = g & 3;
            const __half* src = g_W + (size_t)(w * 32 + row) * KE2 + kc + part * 8;
            uint32_t dst = aWarpBase + buf * ABUF_SZ + row * (AST * 2) + part * 16;
            asm volatile("cp.async.cg.shared.global [%0], [%1], 16;"
                         :: "r"(dst), "l"(src));
        }
        asm volatile("cp.async.commit_group;");
    };
    issueA(0, 0);
    issueA(1, 1);

    // --- stage B: im2col + fp16 split, 8 pixels -> 3 x 16B stores ---
    const float* imgs = data + (size_t)bid * 4 * 3072;
    for (int g = t; g < 1536; g += 640) {
        int j = g / 384, rem = g - j * 384;
        int base = rem * 8;
        int ci = base >> 10, r2 = base & 1023;
        int row = r2 >> 5, cb = r2 & 31;
        int kb  = ci * 64 + (row & 7) * 8;
        int pos = (row >> 3) * 4 + (cb >> 3);
        const float* p = imgs + j * 3072 + base;
        float4 va = *reinterpret_cast<const float4*>(p);
        float4 vb = *reinterpret_cast<const float4*>(p + 4);
        float vv[8] = {va.x, va.y, va.z, va.w, vb.x, vb.y, vb.z, vb.w};
        union { __half2 h2[4]; uint4 u; } t0, t1;
#pragma unroll
        for (int i = 0; i < 4; i++) {
            __half a0 = __float2half_rn(vv[2 * i]);
            __half b0 = __float2half_rn(vv[2 * i + 1]);
            __half a1 = __float2half_rn(vv[2 * i]     - __half2float(a0));
            __half b1 = __float2half_rn(vv[2 * i + 1] - __half2float(b0));
            t0.h2[i] = __halves2half2(a0, b0);
            t1.h2[i] = __halves2half2(a1, b1);
        }
        char* rb = sm + OFF_B + (j * 16 + pos) * (BST * 2);
        *reinterpret_cast<uint4*>(rb + 2 * kb)         = t0.u;
        *reinterpret_cast<uint4*>(rb + 2 * (192 + kb)) = t1.u;
        *reinterpret_cast<uint4*>(rb + 2 * (384 + kb)) = t0.u;
    }
    __syncthreads();   // ONLY block-wide sync before epilogue

    float acc[2][8][4];
#pragma unroll
    for (int mt = 0; mt < 2; mt++)
#pragma unroll
        for (int nt = 0; nt < 8; nt++)
#pragma unroll
            for (int c = 0; c < 4; c++) acc[mt][nt][c] = 0.f;

    const int lm = lane >> 3;
    const uint32_t aAddr = aWarpBase +
        (((lm & 1) * 8 + (lane & 7)) * AST + (lm >> 1) * 8) * 2;
    const uint32_t bAddr = sb + OFF_B +
        (((lm >> 1) * 8 + (lane & 7)) * BST + (lm & 1) * 8) * 2;

#pragma unroll 3
    for (int c = 0; c < NCH; c++) {
        if (c + 1 < NCH) asm volatile("cp.async.wait_group 1;");
        else             asm volatile("cp.async.wait_group 0;");
        __syncwarp();
        if (c + 2 < NCH) issueA(c + 2, (c + 2) % 3);

        const uint32_t aBuf = aAddr + (c % 3) * ABUF_SZ;
#pragma unroll
        for (int ks = 0; ks < 2; ks++) {
            uint32_t a0[4], a1[4];
            uint32_t aBase = aBuf + ks * 32;
            LDSM4(a0[0], a0[1], a0[2], a0[3], aBase);
            LDSM4(a1[0], a1[1], a1[2], a1[3], aBase + 16 * AST * 2);
#pragma unroll
            for (int ntp = 0; ntp < 4; ntp++) {
                uint32_t b[4];
                LDSM4(b[0], b[1], b[2], b[3],
                      bAddr + ntp * (16 * BST * 2) + c * (KC * 2) + ks * 32);
#pragma unroll
                for (int sub = 0; sub < 2; sub++) {
                    int nt = 2 * ntp + sub;
                    asm volatile(
                        "mma.sync.aligned.m16n8k16.row.col.f32.f16.f16.f32 "
                        "{%0,%1,%2,%3},{%4,%5,%6,%7},{%8,%9},{%0,%1,%2,%3};"
                        : "+f"(acc[0][nt][0]), "+f"(acc[0][nt][1]),
                          "+f"(acc[0][nt][2]), "+f"(acc[0][nt][3])
                        : "r"(a0[0]), "r"(a0[1]), "r"(a0[2]), "r"(a0[3]),
                          "r"(b[2 * sub]), "r"(b[2 * sub + 1]));
                    asm volatile(
                        "mma.sync.aligned.m16n8k16.row.col.f32.f16.f16.f32 "
                        "{%0,%1,%2,%3},{%4,%5,%6,%7},{%8,%9},{%0,%1,%2,%3};"
                        : "+f"(acc[1][nt][0]), "+f"(acc[1][nt][1]),
                          "+f"(acc[1][nt][2]), "+f"(acc[1][nt][3])
                        : "r"(a1[0]), "r"(a1[1]), "r"(a1[2]), "r"(a1[3]),
                          "r"(b[2 * sub]), "r"(b[2 * sub + 1]));
                }
            }
        }
    }
    __syncthreads();   // all warps done; A region reusable as scratch

    float* ssq = reinterpret_cast<float*>(sm + OFF_SSQ);
    float* ss2 = reinterpret_cast<float*>(sm + OFF_SS2);
    float* vsm = reinterpret_cast<float*>(sm + OFF_VSM);
    if (t < 64) ssq[t] = 0.f;
    if (t >= 64 && t < 68) ss2[t - 64] = 0.f;
    __syncthreads();

    // ---- epilogue: per-position channel L2-norm ----
    {
        float cs[16];
#pragma unroll
        for (int nt = 0; nt < 8; nt++)
#pragma unroll
            for (int par = 0; par < 2; par++) {
                float s = 0.f;
#pragma unroll
                for (int mt = 0; mt < 2; mt++) {
                    float x0 = acc[mt][nt][par], x1 = acc[mt][nt][2 + par];
                    s = fmaf(x0, x0, s);
                    s = fmaf(x1, x1, s);
                }
                cs[nt * 2 + par] = s;
            }
#pragma unroll
        for (int i = 0; i < 16; i++) {
            cs[i] += __shfl_xor_sync(0xffffffffu, cs[i], 4);
            cs[i] += __shfl_xor_sync(0xffffffffu, cs[i], 8);
            cs[i] += __shfl_xor_sync(0xffffffffu, cs[i], 16);
        }
        if (lane < 4) {
#pragma unroll
            for (int nt = 0; nt < 8; nt++)
#pragma unroll
                for (int par = 0; par < 2; par++)
                    atomicAdd(&ssq[nt * 8 + lane * 2 + par], cs[nt * 2 + par]);
        }
    }
    __syncthreads();
    if (t < 64) ssq[t] = 1.f / fmaxf(sqrtf(ssq[t]), 1e-12f);
    __syncthreads();

    // ---- pool over positions + final channel L2-norm ----
    float sq[4] = {0.f, 0.f, 0.f, 0.f};
#pragma unroll
    for (int mt = 0; mt < 2; mt++)
#pragma unroll
        for (int h = 0; h < 2; h++)
#pragma unroll
            for (int j = 0; j < 4; j++) {
                float s = 0.f;
#pragma unroll
                for (int ntl = 0; ntl < 2; ntl++) {
                    int nt = 2 * j + ntl;
#pragma unroll
                    for (int par = 0; par < 2; par++) {
                        int col = nt * 8 + (lane & 3) * 2 + par;
                        s = fmaf(acc[mt][nt][h * 2 + par], ssq[col], s);
                    }
                }
                s += __shfl_xor_sync(0xffffffffu, s, 1);
                s += __shfl_xor_sync(0xffffffffu, s, 2);
                if ((lane & 3) == 0) {
                    int row = w * 32 + mt * 16 + h * 8 + (lane >> 2);
                    float v = s * 0.0625f;
                    vsm[row * 4 + j] = v;
                    sq[j] = fmaf(v, v, sq[j]);
                }
            }
#pragma unroll
    for (int j = 0; j < 4; j++) {
        sq[j] += __shfl_xor_sync(0xffffffffu, sq[j], 4);
        sq[j] += __shfl_xor_sync(0xffffffffu, sq[j], 8);
        sq[j] += __shfl_xor_sync(0xffffffffu, sq[j], 16);
    }
    if (lane == 0)
#pragma unroll
        for (int j = 0; j < 4; j++) atomicAdd(&ss2[j], sq[j]);
    __syncthreads();
    if (t < 4) ss2[t] = 1.f / fmaxf(sqrtf(ss2[t]), 1e-12f);
    __syncthreads();

    for (int g = t; g < 2560; g += 640) {
        int ch = g >> 2, j = g & 3;
        g_u[(size_t)(4 * bid + j) * CO + ch] = vsm[ch * 4 + j] * ss2[j];
    }
}

// ---------------------------------------------------------------------------
// Sim + greedy: 2 queries per block (support rows shared). 768 threads.
// Block (b, j) covers queries n0=2j, n1=2j+1 (n1 guarded; NQ=75 odd).
// ---------------------------------------------------------------------------
#define QS 644
#define JBLK 38
#define SIMSMT ((63 * QS + 720 * 9 + 810) * 4)   // 191448

__global__ void __launch_bounds__(768) k_sim(float* __restrict__ out) {
    extern __shared__ float smf[];
    float* rows = smf;                    // [63][QS]: 0-8 q0, 9-17 q1, 18-62 sup
    float* psum = smf + 63 * QS;          // [720][9]
    float* simm = psum + 720 * 9;         // [2][5][81]

    const int b = blockIdx.x / JBLK;
    const int j = blockIdx.x % JBLK;
    const int n0 = 2 * j;
    const int nq = (n0 + 1 < NQ_) ? 2 : 1;
    const int t = threadIdx.x;

    const float* q0b = g_u + ((size_t)(b * 80 + WAY_ + n0) * P_) * CO;
    const float* q1b = (nq == 2) ? q0b + (size_t)P_ * CO : q0b;
    const float* sb  = g_u + ((size_t)(b * 80) * P_) * CO;   // 45 contiguous rows
    for (int i = t; i < 63 * 160; i += 768) {
        int r = i / 160, c4 = (i % 160) * 4;
        const float* src;
        if (r < 9)       src = q0b + (size_t)r * CO + c4;
        else if (r < 18) src = q1b + (size_t)(r - 9) * CO + c4;
        else             src = sb + (size_t)(r - 18) * CO + c4;
        *reinterpret_cast<float4*>(&rows[r * QS + c4]) =
            *reinterpret_cast<const float4*>(src);
    }
    __syncthreads();

    if (t < 720) {
        const int q = t / 360, r = t % 360;
        const int m = r / 72, rr = r % 72;
        const int tt = rr >> 3, ss = rr & 7;
        const int k0 = ss * 80;
        const float* s0 = &rows[(18 + m * 9 + (tt / 3) * 3 + 0) * QS + k0];
        const float* s1 = s0 + QS;
        const float* s2 = s1 + QS;
        const float* qq0 = &rows[(q * 9 + (tt % 3) * 3 + 0) * QS + k0];
        const float* qq1 = qq0 + QS;
        const float* qq2 = qq1 + QS;
        float a00 = 0.f, a01 = 0.f, a02 = 0.f;
        float a10 = 0.f, a11 = 0.f, a12 = 0.f;
        float a20 = 0.f, a21 = 0.f, a22 = 0.f;
#pragma unroll 2
        for (int k = 0; k < 80; k += 4) {
            float4 sv0 = *reinterpret_cast<const float4*>(s0 + k);
            float4 sv1 = *reinterpret_cast<const float4*>(s1 + k);
            float4 sv2 = *reinterpret_cast<const float4*>(s2 + k);
            float4 qv0 = *reinterpret_cast<const float4*>(qq0 + k);
            float4 qv1 = *reinterpret_cast<const float4*>(qq1 + k);
            float4 qv2 = *reinterpret_cast<const float4*>(qq2 + k);
            a00 = fmaf(sv0.x, qv0.x, a00); a00 = fmaf(sv0.y, qv0.y, a00);
            a00 = fmaf(sv0.z, qv0.z, a00); a00 = fmaf(sv0.w, qv0.w, a00);
            a01 = fmaf(sv0.x, qv1.x, a01); a01 = fmaf(sv0.y, qv1.y, a01);
            a01 = fmaf(sv0.z, qv1.z, a01); a01 = fmaf(sv0.w, qv1.w, a01);
            a02 = fmaf(sv0.x, qv2.x, a02); a02 = fmaf(sv0.y, qv2.y, a02);
            a02 = fmaf(sv0.z, qv2.z, a02); a02 = fmaf(sv0.w, qv2.w, a02);
            a10 = fmaf(sv1.x, qv0.x, a10); a10 = fmaf(sv1.y, qv0.y, a10);
            a10 = fmaf(sv1.z, qv0.z, a10); a10 = fmaf(sv1.w, qv0.w, a10);
            a11 = fmaf(sv1.x, qv1.x, a11); a11 = fmaf(sv1.y, qv1.y, a11);
            a11 = fmaf(sv1.z, qv1.z, a11); a11 = fmaf(sv1.w, qv1.w, a11);
            a12 = fmaf(sv1.x, qv2.x, a12); a12 = fmaf(sv1.y, qv2.y, a12);
            a12 = fmaf(sv1.z, qv2.z, a12); a12 = fmaf(sv1.w, qv2.w, a12);
            a20 = fmaf(sv2.x, qv0.x, a20); a20 = fmaf(sv2.y, qv0.y, a20);
            a20 = fmaf(sv2.z, qv0.z, a20); a20 = fmaf(sv2.w, qv0.w, a20);
            a21 = fmaf(sv2.x, qv1.x, a21); a21 = fmaf(sv2.y, qv1.y, a21);
            a21 = fmaf(sv2.z, qv1.z, a21); a21 = fmaf(sv2.w, qv1.w, a21);
            a22 = fmaf(sv2.x, qv2.x, a22); a22 = fmaf(sv2.y, qv2.y, a22);
            a22 = fmaf(sv2.z, qv2.z, a22); a22 = fmaf(sv2.w, qv2.w, a22);
        }
        float* pr = &psum[t * 9];
        pr[0] = a00; pr[1] = a01; pr[2] = a02;
        pr[3] = a10; pr[4] = a11; pr[5] = a12;
        pr[6] = a20; pr[7] = a21; pr[8] = a22;
    }
    __syncthreads();

    for (int i = t; i < 810; i += 768) {
        int q = i / 405, rem = i % 405;
        int m = rem / 81, e = rem % 81;
        int h = e / 9, wq = e % 9;
        int tile = (h / 3) * 3 + wq / 3;
        int el = (h % 3) * 3 + (wq % 3);
        float s = 0.f;
#pragma unroll
        for (int ss = 0; ss < 8; ss++)
            s += psum[(q * 360 + m * 72 + tile * 8 + ss) * 9 + el];
        simm[i] = s;
    }
    __syncthreads();

    // 10 greedy warps: warp = q*5 + m
    const int wp = t >> 5, lane = t & 31;
    if (wp < 2 * WAY_) {
        const int q = wp / WAY_, m = wp % WAY_;
        if (q < nq) {
            const float* sv = &simm[(q * WAY_ + m) * 81];
            float v0 = sv[lane];
            float v1 = sv[lane + 32];
            float v2 = (lane + 64 < 81) ? sv[lane + 64] : -1e30f;
            unsigned rmask = 0x1FFu, cmask = 0x1FFu;
            float totalv = 0.f, beta = 1.f;
            for (int it = 0; it < 9; it++) {
                float bv = -1e30f;
                int bidx = 999;
                int jj = lane;
                if (((rmask >> (jj / 9)) & 1) && ((cmask >> (jj % 9)) & 1)) {
                    bv = v0; bidx = jj;
                }
                jj = lane + 32;
                if (((rmask >> (jj / 9)) & 1) && ((cmask >> (jj % 9)) & 1)) {
                    if (v1 > bv || (v1 == bv && jj < bidx)) { bv = v1; bidx = jj; }
                }
                jj = lane + 64;
                if (jj < 81 && ((rmask >> (jj / 9)) & 1) && ((cmask >> (jj % 9)) & 1)) {
                    if (v2 > bv || (v2 == bv && jj < bidx)) { bv = v2; bidx = jj; }
                }
#pragma unroll
                for (int off = 16; off; off >>= 1) {
                    float ov = __shfl_xor_sync(0xffffffffu, bv, off);
                    int   oi = __shfl_xor_sync(0xffffffffu, bidx, off);
                    if (ov > bv || (ov == bv && oi < bidx)) { bv = ov; bidx = oi; }
                }
                totalv = fmaf(fmaxf(bv, 0.f), beta, totalv);
                beta *= 0.5f;
                rmask &= ~(1u << (bidx / 9));
                cmask &= ~(1u << (bidx % 9));
            }
            if (lane == 0)
                out[((size_t)b * NQ_ + n0 + q) * WAY_ + m] = totalv;
        }
    }
}

// ---------------------------------------------------------------------------
extern "C" void kernel_launch(void* const* d_in, const int* in_sizes, int n_in,
                              void* d_out, int out_size) {
    const float* data   = (const float*)d_in[0];
    const float* conv_w = (const float*)d_in[1];
    (void)in_sizes; (void)n_in; (void)out_size;

    static bool attr_set = false;
    if (!attr_set) {
        cudaFuncSetAttribute(k_gemm, cudaFuncAttributeMaxDynamicSharedMemorySize, SMT);
        cudaFuncSetAttribute(k_sim, cudaFuncAttributeMaxDynamicSharedMemorySize, SIMSMT);
        attr_set = true;
    }

    k_prepw<<<(CO * KD + 255) / 256, 256>>>(conv_w);
    k_gemm<<<NTOT / TNB, 640, SMT>>>(data);
    k_sim<<<B_ * JBLK, 768, SIMSMT>>>((float*)d_out);
}

// round 15
// speedup vs baseline: 1.1817x; 1.0985x over previous
#include <cuda_runtime.h>
#include <cuda_fp16.h>
#include <cstdint>
#include <math.h>

// ---------------- problem constants ----------------
#define NS   5760
#define CO   640
#define KD   192
#define B_   8
#define WAY_ 5
#define NQ_  75
#define P_   9
#define NTOT (NS * 16)       // 92160
#define KW   384             // W gmem cols: [w0 | w1]
#define TNB  64              // N per block = 4 images
#define KC   32              // K halves per chunk
#define NCH  12              // 384 / 32

// ---------------- device scratch ----------------
__device__ __align__(128) __half g_W[(size_t)CO * KW];     // 492 KB
__device__ float g_u[(size_t)NS * CO];

__device__ __forceinline__ uint32_t smem_u32(const void* p) {
    uint32_t a;
    asm("{ .reg .u64 t; cvta.to.shared.u64 t, %1; cvt.u32.u64 %0, t; }"
        : "=r"(a) : "l"(p));
    return a;
}

// ---------------------------------------------------------------------------
// Prep W: fp16 split, K-concat [w0 | w1]
// ---------------------------------------------------------------------------
__global__ void k_prepw(const float* __restrict__ w) {
    int i = blockIdx.x * 256 + threadIdx.x;
    if (i >= CO * KD) return;
    int ch = i / KD, k = i % KD;
    float v = w[i];
    __half h0 = __float2half_rn(v);
    __half h1 = __float2half_rn(v - __half2float(h0));
    size_t b = (size_t)ch * KW;
    g_W[b + k]       = h0;
    g_W[b + 192 + k] = h1;
}

// ---------------------------------------------------------------------------
// Fused im2col + GEMM + norms. A dedup edition: B smem = [x0|x1] (384 cols);
// even A chunks (w0_i) MMA against both x0_i and x1_i (A frags reused),
// odd chunks (w1_i) against x0_i. Per-warp triple-buffered A, one block sync.
// ---------------------------------------------------------------------------
#define BST      392                      // B row stride (halves): 784 B
#define AST      40                       // A row stride (halves): 80 B
#define OFF_B    0
#define BSZ      (TNB * BST * 2)          // 50176
#define OFF_A    BSZ
#define ABUF_SZ  (32 * AST * 2)           // 2560 per warp-buffer
#define AWARP_SZ (3 * ABUF_SZ)            // 7680 per warp
#define SMT      (OFF_A + 20 * AWARP_SZ)  // 203776
#define OFF_SSQ  OFF_A
#define OFF_SS2  (OFF_A + 256)
#define OFF_VSM  (OFF_A + 272)

#define LDSM4(r0, r1, r2, r3, ad) \
    asm volatile("ldmatrix.sync.aligned.m8n8.x4.shared.b16 {%0,%1,%2,%3},[%4];" \
                 : "=r"(r0), "=r"(r1), "=r"(r2), "=r"(r3) : "r"(ad))

#define MMA(accp, a, b0, b1) \
    asm volatile( \
        "mma.sync.aligned.m16n8k16.row.col.f32.f16.f16.f32 " \
        "{%0,%1,%2,%3},{%4,%5,%6,%7},{%8,%9},{%0,%1,%2,%3};" \
        : "+f"((accp)[0]), "+f"((accp)[1]), "+f"((accp)[2]), "+f"((accp)[3]) \
        : "r"((a)[0]), "r"((a)[1]), "r"((a)[2]), "r"((a)[3]), "r"(b0), "r"(b1))

__global__ void __launch_bounds__(640, 1) k_gemm(const float* __restrict__ data) {
    extern __shared__ char sm[];
    const int t = threadIdx.x, w = t >> 5, lane = t & 31;
    const int bid = blockIdx.x;
    const uint32_t sb = smem_u32(sm);
    const uint32_t aWarpBase = sb + OFF_A + w * AWARP_SZ;

    // --- per-warp A chunk c: w0_(c/2) if even, w1_(c/2) if odd; 32 rows x 64B ---
    auto issueA = [&](int c, int buf) {
        const int kc = ((c & 1) ? 192 : 0) + (c >> 1) * KC;
#pragma unroll
        for (int i = 0; i < 4; i++) {
            int g = lane + 32 * i;
            int row = g >> 2, part = g & 3;
            const __half* src = g_W + (size_t)(w * 32 + row) * KW + kc + part * 8;
            uint32_t dst = aWarpBase + buf * ABUF_SZ + row * (AST * 2) + part * 16;
            asm volatile("cp.async.cg.shared.global [%0], [%1], 16;"
                         :: "r"(dst), "l"(src));
        }
        asm volatile("cp.async.commit_group;");
    };
    issueA(0, 0);
    issueA(1, 1);

    // --- stage B: im2col + fp16 split [x0 | x1], 8 pixels -> 2 x 16B stores ---
    const float* imgs = data + (size_t)bid * 4 * 3072;
    for (int g = t; g < 1536; g += 640) {
        int j = g / 384, rem = g - j * 384;
        int base = rem * 8;
        int ci = base >> 10, r2 = base & 1023;
        int row = r2 >> 5, cb = r2 & 31;
        int kb  = ci * 64 + (row & 7) * 8;
        int pos = (row >> 3) * 4 + (cb >> 3);
        const float* p = imgs + j * 3072 + base;
        float4 va = *reinterpret_cast<const float4*>(p);
        float4 vb = *reinterpret_cast<const float4*>(p + 4);
        float vv[8] = {va.x, va.y, va.z, va.w, vb.x, vb.y, vb.z, vb.w};
        union { __half2 h2[4]; uint4 u; } t0, t1;
#pragma unroll
        for (int i = 0; i < 4; i++) {
            __half a0 = __float2half_rn(vv[2 * i]);
            __half b0 = __float2half_rn(vv[2 * i + 1]);
            __half a1 = __float2half_rn(vv[2 * i]     - __half2float(a0));
            __half b1 = __float2half_rn(vv[2 * i + 1] - __half2float(b0));
            t0.h2[i] = __halves2half2(a0, b0);
            t1.h2[i] = __halves2half2(a1, b1);
        }
        char* rb = sm + OFF_B + (j * 16 + pos) * (BST * 2);
        *reinterpret_cast<uint4*>(rb + 2 * kb)         = t0.u;
        *reinterpret_cast<uint4*>(rb + 2 * (192 + kb)) = t1.u;
    }
    __syncthreads();   // ONLY block-wide sync before epilogue

    float acc[2][8][4];
#pragma unroll
    for (int mt = 0; mt < 2; mt++)
#pragma unroll
        for (int nt = 0; nt < 8; nt++)
#pragma unroll
            for (int c = 0; c < 4; c++) acc[mt][nt][c] = 0.f;

    const int lm = lane >> 3;
    const uint32_t aAddr = aWarpBase +
        (((lm & 1) * 8 + (lane & 7)) * AST + (lm >> 1) * 8) * 2;
    const uint32_t bAddr = sb + OFF_B +
        (((lm >> 1) * 8 + (lane & 7)) * BST + (lm & 1) * 8) * 2;

    for (int c = 0; c < NCH; c++) {
        if (c + 1 < NCH) asm volatile("cp.async.wait_group 1;");
        else             asm volatile("cp.async.wait_group 0;");
        __syncwarp();
        if (c + 2 < NCH) issueA(c + 2, (c + 2) % 3);

        const uint32_t aBuf = aAddr + (c % 3) * ABUF_SZ;
        const int i32 = (c >> 1) * KC;           // base-K block col (halves)
        const bool even = (c & 1) == 0;
#pragma unroll
        for (int ks = 0; ks < 2; ks++) {
            uint32_t a0[4], a1[4];
            uint32_t aBase = aBuf + ks * 32;
            LDSM4(a0[0], a0[1], a0[2], a0[3], aBase);
            LDSM4(a1[0], a1[1], a1[2], a1[3], aBase + 16 * AST * 2);
            // B block 1: x0_i
#pragma unroll
            for (int ntp = 0; ntp < 4; ntp++) {
                uint32_t b[4];
                LDSM4(b[0], b[1], b[2], b[3],
                      bAddr + ntp * (16 * BST * 2) + (i32 + ks * 16) * 2);
#pragma unroll
                for (int sub = 0; sub < 2; sub++) {
                    MMA(acc[0][2 * ntp + sub], a0, b[2 * sub], b[2 * sub + 1]);
                    MMA(acc[1][2 * ntp + sub], a1, b[2 * sub], b[2 * sub + 1]);
                }
            }
            // B block 2 (even chunks only): x1_i, reusing the same A frags
            if (even) {
#pragma unroll
                for (int ntp = 0; ntp < 4; ntp++) {
                    uint32_t b[4];
                    LDSM4(b[0], b[1], b[2], b[3],
                          bAddr + ntp * (16 * BST * 2) + (192 + i32 + ks * 16) * 2);
#pragma unroll
                    for (int sub = 0; sub < 2; sub++) {
                        MMA(acc[0][2 * ntp + sub], a0, b[2 * sub], b[2 * sub + 1]);
                        MMA(acc[1][2 * ntp + sub], a1, b[2 * sub], b[2 * sub + 1]);
                    }
                }
            }
        }
    }
    __syncthreads();   // all warps done; A region reusable as scratch

    float* ssq = reinterpret_cast<float*>(sm + OFF_SSQ);
    float* ss2 = reinterpret_cast<float*>(sm + OFF_SS2);
    float* vsm = reinterpret_cast<float*>(sm + OFF_VSM);
    if (t < 64) ssq[t] = 0.f;
    if (t >= 64 && t < 68) ss2[t - 64] = 0.f;
    __syncthreads();

    // ---- epilogue: per-position channel L2-norm ----
    {
        float cs[16];
#pragma unroll
        for (int nt = 0; nt < 8; nt++)
#pragma unroll
            for (int par = 0; par < 2; par++) {
                float s = 0.f;
#pragma unroll
                for (int mt = 0; mt < 2; mt++) {
                    float x0 = acc[mt][nt][par], x1 = acc[mt][nt][2 + par];
                    s = fmaf(x0, x0, s);
                    s = fmaf(x1, x1, s);
                }
                cs[nt * 2 + par] = s;
            }
#pragma unroll
        for (int i = 0; i < 16; i++) {
            cs[i] += __shfl_xor_sync(0xffffffffu, cs[i], 4);
            cs[i] += __shfl_xor_sync(0xffffffffu, cs[i], 8);
            cs[i] += __shfl_xor_sync(0xffffffffu, cs[i], 16);
        }
        if (lane < 4) {
#pragma unroll
            for (int nt = 0; nt < 8; nt++)
#pragma unroll
                for (int par = 0; par < 2; par++)
                    atomicAdd(&ssq[nt * 8 + lane * 2 + par], cs[nt * 2 + par]);
        }
    }
    __syncthreads();
    if (t < 64) ssq[t] = 1.f / fmaxf(sqrtf(ssq[t]), 1e-12f);
    __syncthreads();

    // ---- pool over positions + final channel L2-norm ----
    float sq[4] = {0.f, 0.f, 0.f, 0.f};
#pragma unroll
    for (int mt = 0; mt < 2; mt++)
#pragma unroll
        for (int h = 0; h < 2; h++)
#pragma unroll
            for (int j = 0; j < 4; j++) {
                float s = 0.f;
#pragma unroll
                for (int ntl = 0; ntl < 2; ntl++) {
                    int nt = 2 * j + ntl;
#pragma unroll
                    for (int par = 0; par < 2; par++) {
                        int col = nt * 8 + (lane & 3) * 2 + par;
                        s = fmaf(acc[mt][nt][h * 2 + par], ssq[col], s);
                    }
                }
                s += __shfl_xor_sync(0xffffffffu, s, 1);
                s += __shfl_xor_sync(0xffffffffu, s, 2);
                if ((lane & 3) == 0) {
                    int row = w * 32 + mt * 16 + h * 8 + (lane >> 2);
                    float v = s * 0.0625f;
                    vsm[row * 4 + j] = v;
                    sq[j] = fmaf(v, v, sq[j]);
                }
            }
#pragma unroll
    for (int j = 0; j < 4; j++) {
        sq[j] += __shfl_xor_sync(0xffffffffu, sq[j], 4);
        sq[j] += __shfl_xor_sync(0xffffffffu, sq[j], 8);
        sq[j] += __shfl_xor_sync(0xffffffffu, sq[j], 16);
    }
    if (lane == 0)
#pragma unroll
        for (int j = 0; j < 4; j++) atomicAdd(&ss2[j], sq[j]);
    __syncthreads();
    if (t < 4) ss2[t] = 1.f / fmaxf(sqrtf(ss2[t]), 1e-12f);
    __syncthreads();

    for (int g = t; g < 2560; g += 640) {
        int ch = g >> 2, j = g & 3;
        g_u[(size_t)(4 * bid + j) * CO + ch] = vsm[ch * 4 + j] * ss2[j];
    }
}

// ---------------------------------------------------------------------------
// Sim + greedy: 2 queries per block (R14, passing). 768 threads.
// ---------------------------------------------------------------------------
#define QS 644
#define JBLK 38
#define SIMSMT ((63 * QS + 720 * 9 + 810) * 4)   // 191448

__global__ void __launch_bounds__(768) k_sim(float* __restrict__ out) {
    extern __shared__ float smf[];
    float* rows = smf;                    // [63][QS]: 0-8 q0, 9-17 q1, 18-62 sup
    float* psum = smf + 63 * QS;          // [720][9]
    float* simm = psum + 720 * 9;         // [2][5][81]

    const int b = blockIdx.x / JBLK;
    const int j = blockIdx.x % JBLK;
    const int n0 = 2 * j;
    const int nq = (n0 + 1 < NQ_) ? 2 : 1;
    const int t = threadIdx.x;

    const float* q0b = g_u + ((size_t)(b * 80 + WAY_ + n0) * P_) * CO;
    const float* q1b = (nq == 2) ? q0b + (size_t)P_ * CO : q0b;
    const float* sb  = g_u + ((size_t)(b * 80) * P_) * CO;
    for (int i = t; i < 63 * 160; i += 768) {
        int r = i / 160, c4 = (i % 160) * 4;
        const float* src;
        if (r < 9)       src = q0b + (size_t)r * CO + c4;
        else if (r < 18) src = q1b + (size_t)(r - 9) * CO + c4;
        else             src = sb + (size_t)(r - 18) * CO + c4;
        *reinterpret_cast<float4*>(&rows[r * QS + c4]) =
            *reinterpret_cast<const float4*>(src);
    }
    __syncthreads();

    if (t < 720) {
        const int q = t / 360, r = t % 360;
        const int m = r / 72, rr = r % 72;
        const int tt = rr >> 3, ss = rr & 7;
        const int k0 = ss * 80;
        const float* s0 = &rows[(18 + m * 9 + (tt / 3) * 3 + 0) * QS + k0];
        const float* s1 = s0 + QS;
        const float* s2 = s1 + QS;
        const float* qq0 = &rows[(q * 9 + (tt % 3) * 3 + 0) * QS + k0];
        const float* qq1 = qq0 + QS;
        const float* qq2 = qq1 + QS;
        float a00 = 0.f, a01 = 0.f, a02 = 0.f;
        float a10 = 0.f, a11 = 0.f, a12 = 0.f;
        float a20 = 0.f, a21 = 0.f, a22 = 0.f;
#pragma unroll 2
        for (int k = 0; k < 80; k += 4) {
            float4 sv0 = *reinterpret_cast<const float4*>(s0 + k);
            float4 sv1 = *reinterpret_cast<const float4*>(s1 + k);
            float4 sv2 = *reinterpret_cast<const float4*>(s2 + k);
            float4 qv0 = *reinterpret_cast<const float4*>(qq0 + k);
            float4 qv1 = *reinterpret_cast<const float4*>(qq1 + k);
            float4 qv2 = *reinterpret_cast<const float4*>(qq2 + k);
            a00 = fmaf(sv0.x, qv0.x, a00); a00 = fmaf(sv0.y, qv0.y, a00);
            a00 = fmaf(sv0.z, qv0.z, a00); a00 = fmaf(sv0.w, qv0.w, a00);
            a01 = fmaf(sv0.x, qv1.x, a01); a01 = fmaf(sv0.y, qv1.y, a01);
            a01 = fmaf(sv0.z, qv1.z, a01); a01 = fmaf(sv0.w, qv1.w, a01);
            a02 = fmaf(sv0.x, qv2.x, a02); a02 = fmaf(sv0.y, qv2.y, a02);
            a02 = fmaf(sv0.z, qv2.z, a02); a02 = fmaf(sv0.w, qv2.w, a02);
            a10 = fmaf(sv1.x, qv0.x, a10); a10 = fmaf(sv1.y, qv0.y, a10);
            a10 = fmaf(sv1.z, qv0.z, a10); a10 = fmaf(sv1.w, qv0.w, a10);
            a11 = fmaf(sv1.x, qv1.x, a11); a11 = fmaf(sv1.y, qv1.y, a11);
            a11 = fmaf(sv1.z, qv1.z, a11); a11 = fmaf(sv1.w, qv1.w, a11);
            a12 = fmaf(sv1.x, qv2.x, a12); a12 = fmaf(sv1.y, qv2.y, a12);
            a12 = fmaf(sv1.z, qv2.z, a12); a12 = fmaf(sv1.w, qv2.w, a12);
            a20 = fmaf(sv2.x, qv0.x, a20); a20 = fmaf(sv2.y, qv0.y, a20);
            a20 = fmaf(sv2.z, qv0.z, a20); a20 = fmaf(sv2.w, qv0.w, a20);
            a21 = fmaf(sv2.x, qv1.x, a21); a21 = fmaf(sv2.y, qv1.y, a21);
            a21 = fmaf(sv2.z, qv1.z, a21); a21 = fmaf(sv2.w, qv1.w, a21);
            a22 = fmaf(sv2.x, qv2.x, a22); a22 = fmaf(sv2.y, qv2.y, a22);
            a22 = fmaf(sv2.z, qv2.z, a22); a22 = fmaf(sv2.w, qv2.w, a22);
        }
        float* pr = &psum[t * 9];
        pr[0] = a00; pr[1] = a01; pr[2] = a02;
        pr[3] = a10; pr[4] = a11; pr[5] = a12;
        pr[6] = a20; pr[7] = a21; pr[8] = a22;
    }
    __syncthreads();

    for (int i = t; i < 810; i += 768) {
        int q = i / 405, rem = i % 405;
        int m = rem / 81, e = rem % 81;
        int h = e / 9, wq = e % 9;
        int tile = (h / 3) * 3 + wq / 3;
        int el = (h % 3) * 3 + (wq % 3);
        float s = 0.f;
#pragma unroll
        for (int ss = 0; ss < 8; ss++)
            s += psum[(q * 360 + m * 72 + tile * 8 + ss) * 9 + el];
        simm[i] = s;
    }
    __syncthreads();

    const int wp = t >> 5, lane = t & 31;
    if (wp < 2 * WAY_) {
        const int q = wp / WAY_, m = wp % WAY_;
        if (q < nq) {
            const float* sv = &simm[(q * WAY_ + m) * 81];
            float v0 = sv[lane];
            float v1 = sv[lane + 32];
            float v2 = (lane + 64 < 81) ? sv[lane + 64] : -1e30f;
            unsigned rmask = 0x1FFu, cmask = 0x1FFu;
            float totalv = 0.f, beta = 1.f;
            for (int it = 0; it < 9; it++) {
                float bv = -1e30f;
                int bidx = 999;
                int jj = lane;
                if (((rmask >> (jj / 9)) & 1) && ((cmask >> (jj % 9)) & 1)) {
                    bv = v0; bidx = jj;
                }
                jj = lane + 32;
                if (((rmask >> (jj / 9)) & 1) && ((cmask >> (jj % 9)) & 1)) {
                    if (v1 > bv || (v1 == bv && jj < bidx)) { bv = v1; bidx = jj; }
                }
                jj = lane + 64;
                if (jj < 81 && ((rmask >> (jj / 9)) & 1) && ((cmask >> (jj % 9)) & 1)) {
                    if (v2 > bv || (v2 == bv && jj < bidx)) { bv = v2; bidx = jj; }
                }
#pragma unroll
                for (int off = 16; off; off >>= 1) {
                    float ov = __shfl_xor_sync(0xffffffffu, bv, off);
                    int   oi = __shfl_xor_sync(0xffffffffu, bidx, off);
                    if (ov > bv || (ov == bv && oi < bidx)) { bv = ov; bidx = oi; }
                }
                totalv = fmaf(fmaxf(bv, 0.f), beta, totalv);
                beta *= 0.5f;
                rmask &= ~(1u << (bidx / 9));
                cmask &= ~(1u << (bidx % 9));
            }
            if (lane == 0)
                out[((size_t)b * NQ_ + n0 + q) * WAY_ + m] = totalv;
        }
    }
}

// ---------------------------------------------------------------------------
extern "C" void kernel_launch(void* const* d_in, const int* in_sizes, int n_in,
                              void* d_out, int out_size) {
    const float* data   = (const float*)d_in[0];
    const float* conv_w = (const float*)d_in[1];
    (void)in_sizes; (void)n_in; (void)out_size;

    static bool attr_set = false;
    if (!attr_set) {
        cudaFuncSetAttribute(k_gemm, cudaFuncAttributeMaxDynamicSharedMemorySize, SMT);
        cudaFuncSetAttribute(k_sim, cudaFuncAttributeMaxDynamicSharedMemorySize, SIMSMT);
        attr_set = true;
    }

    k_prepw<<<(CO * KD + 255) / 256, 256>>>(conv_w);
    k_gemm<<<NTOT / TNB, 640, SMT>>>(data);
    k_sim<<<B_ * JBLK, 768, SIMSMT>>>((float*)d_out);
}

// round 17
// speedup vs baseline: 1.2076x; 1.0220x over previous
#include <cuda_runtime.h>
#include <cuda_fp16.h>
#include <cstdint>
#include <math.h>

// ---------------- problem constants ----------------
#define NS   5760
#define CO   640
#define KD   192
#define B_   8
#define WAY_ 5
#define NQ_  75
#define P_   9
#define NTOT   (NS * 16)     // 92160
#define NTILES 1440          // NTOT / 64
#define GRID_G 152           // persistent blocks (1/SM)
#define KW   384             // W gmem cols: [w0 | w1]
#define TNB  64              // N per tile = 4 images
#define KC   32              // K halves per chunk
#define NCH  12              // 384 / 32

// ---------------- device scratch ----------------
__device__ __align__(128) __half g_W[(size_t)CO * KW];     // 492 KB
__device__ float g_u[(size_t)NS * CO];

__device__ __forceinline__ uint32_t smem_u32(const void* p) {
    uint32_t a;
    asm("{ .reg .u64 t; cvta.to.shared.u64 t, %1; cvt.u32.u64 %0, t; }"
        : "=r"(a) : "l"(p));
    return a;
}

// ---------------------------------------------------------------------------
// Prep W: fp16 split, K-concat [w0 | w1]
// ---------------------------------------------------------------------------
__global__ void k_prepw(const float* __restrict__ w) {
    int i = blockIdx.x * 256 + threadIdx.x;
    if (i >= CO * KD) return;
    int ch = i / KD, k = i % KD;
    float v = w[i];
    __half h0 = __float2half_rn(v);
    __half h1 = __float2half_rn(v - __half2float(h0));
    size_t b = (size_t)ch * KW;
    g_W[b + k]       = h0;
    g_W[b + 192 + k] = h1;
}

// ---------------------------------------------------------------------------
// Persistent fused im2col + GEMM + norms. grid=152, ~9.5 tiles/block.
// R15 mainloop verbatim (triple-buffered per-warp A, A-dedup dual-B);
// next tile's A0/A1 prefetched during the epilogue. Scratch in B region.
// ---------------------------------------------------------------------------
#define BST      392                      // B row stride (halves): 784 B
#define AST      40                       // A row stride (halves): 80 B
#define OFF_B    0
#define BSZ      (TNB * BST * 2)          // 50176
#define OFF_A    BSZ
#define ABUF_SZ  (32 * AST * 2)           // 2560 per warp-buffer
#define AWARP_SZ (3 * ABUF_SZ)            // 7680 per warp
#define SMT      (OFF_A + 20 * AWARP_SZ)  // 203776
// epilogue scratch in B region (B free after mainloop; A region stays live)
#define OFF_SSQ  OFF_B
#define OFF_SS2  (OFF_B + 256)
#define OFF_VSM  (OFF_B + 272)

#define LDSM4(r0, r1, r2, r3, ad) \
    asm volatile("ldmatrix.sync.aligned.m8n8.x4.shared.b16 {%0,%1,%2,%3},[%4];" \
                 : "=r"(r0), "=r"(r1), "=r"(r2), "=r"(r3) : "r"(ad))

#define MMA(accp, a, b0, b1) \
    asm volatile( \
        "mma.sync.aligned.m16n8k16.row.col.f32.f16.f16.f32 " \
        "{%0,%1,%2,%3},{%4,%5,%6,%7},{%8,%9},{%0,%1,%2,%3};" \
        : "+f"((accp)[0]), "+f"((accp)[1]), "+f"((accp)[2]), "+f"((accp)[3]) \
        : "r"((a)[0]), "r"((a)[1]), "r"((a)[2]), "r"((a)[3]), "r"(b0), "r"(b1))

__global__ void __launch_bounds__(640, 1) k_gemm(const float* __restrict__ data) {
    extern __shared__ char sm[];
    const int t = threadIdx.x, w = t >> 5, lane = t & 31;
    const uint32_t sb = smem_u32(sm);
    const uint32_t aWarpBase = sb + OFF_A + w * AWARP_SZ;

    // --- per-warp A chunk c: w0_(c/2) even / w1_(c/2) odd; 32 rows x 64B ---
    auto issueA = [&](int c, int buf) {
        const int kc = ((c & 1) ? 192 : 0) + (c >> 1) * KC;
#pragma unroll
        for (int i = 0; i < 4; i++) {
            int g = lane + 32 * i;
            int row = g >> 2, part = g & 3;
            const __half* src = g_W + (size_t)(w * 32 + row) * KW + kc + part * 8;
            uint32_t dst = aWarpBase + buf * ABUF_SZ + row * (AST * 2) + part * 16;
            asm volatile("cp.async.cg.shared.global [%0], [%1], 16;"
                         :: "r"(dst), "l"(src));
        }
        asm volatile("cp.async.commit_group;");
    };

    const int lm = lane >> 3;
    const uint32_t aAddr = aWarpBase +
        (((lm & 1) * 8 + (lane & 7)) * AST + (lm >> 1) * 8) * 2;
    const uint32_t bAddr = sb + OFF_B +
        (((lm >> 1) * 8 + (lane & 7)) * BST + (lm & 1) * 8) * 2;

    float* ssq = reinterpret_cast<float*>(sm + OFF_SSQ);
    float* ss2 = reinterpret_cast<float*>(sm + OFF_SS2);
    float* vsm = reinterpret_cast<float*>(sm + OFF_VSM);

    issueA(0, 0);
    issueA(1, 1);

    for (int jj = blockIdx.x; jj < NTILES; jj += GRID_G) {
        // --- stage B: im2col + fp16 split [x0 | x1] directly from gmem ---
        const float* imgs = data + (size_t)jj * 4 * 3072;
        for (int g = t; g < 1536; g += 640) {
            int j = g / 384, rem = g - j * 384;
            int base = rem * 8;
            int ci = base >> 10, r2 = base & 1023;
            int row = r2 >> 5, cb = r2 & 31;
            int kb  = ci * 64 + (row & 7) * 8;
            int pos = (row >> 3) * 4 + (cb >> 3);
            const float* p = imgs + j * 3072 + base;
            float4 va = *reinterpret_cast<const float4*>(p);
            float4 vb = *reinterpret_cast<const float4*>(p + 4);
            float vv[8] = {va.x, va.y, va.z, va.w, vb.x, vb.y, vb.z, vb.w};
            union { __half2 h2[4]; uint4 u; } t0, t1;
#pragma unroll
            for (int i = 0; i < 4; i++) {
                __half a0 = __float2half_rn(vv[2 * i]);
                __half b0 = __float2half_rn(vv[2 * i + 1]);
                __half a1 = __float2half_rn(vv[2 * i]     - __half2float(a0));
                __half b1 = __float2half_rn(vv[2 * i + 1] - __half2float(b0));
                t0.h2[i] = __halves2half2(a0, b0);
                t1.h2[i] = __halves2half2(a1, b1);
            }
            char* rb = sm + OFF_B + (j * 16 + pos) * (BST * 2);
            *reinterpret_cast<uint4*>(rb + 2 * kb)         = t0.u;
            *reinterpret_cast<uint4*>(rb + 2 * (192 + kb)) = t1.u;
        }
        __syncthreads();   // B tile visible to all warps

        float acc[2][8][4];
#pragma unroll
        for (int mt = 0; mt < 2; mt++)
#pragma unroll
            for (int nt = 0; nt < 8; nt++)
#pragma unroll
                for (int c = 0; c < 4; c++) acc[mt][nt][c] = 0.f;

        // --- mainloop (R15 verbatim): triple-buffered A, dual-B on even ---
        for (int c = 0; c < NCH; c++) {
            if (c + 1 < NCH) asm volatile("cp.async.wait_group 1;");
            else             asm volatile("cp.async.wait_group 0;");
            __syncwarp();
            if (c + 2 < NCH) issueA(c + 2, (c + 2) % 3);

            const uint32_t aBuf = aAddr + (c % 3) * ABUF_SZ;
            const int i32 = (c >> 1) * KC;
            const bool even = (c & 1) == 0;
#pragma unroll
            for (int ks = 0; ks < 2; ks++) {
                uint32_t a0[4], a1[4];
                uint32_t aBase = aBuf + ks * 32;
                LDSM4(a0[0], a0[1], a0[2], a0[3], aBase);
                LDSM4(a1[0], a1[1], a1[2], a1[3], aBase + 16 * AST * 2);
#pragma unroll
                for (int ntp = 0; ntp < 4; ntp++) {
                    uint32_t b[4];
                    LDSM4(b[0], b[1], b[2], b[3],
                          bAddr + ntp * (16 * BST * 2) + (i32 + ks * 16) * 2);
#pragma unroll
                    for (int sub = 0; sub < 2; sub++) {
                        MMA(acc[0][2 * ntp + sub], a0, b[2 * sub], b[2 * sub + 1]);
                        MMA(acc[1][2 * ntp + sub], a1, b[2 * sub], b[2 * sub + 1]);
                    }
                }
                if (even) {
#pragma unroll
                    for (int ntp = 0; ntp < 4; ntp++) {
                        uint32_t b[4];
                        LDSM4(b[0], b[1], b[2], b[3],
                              bAddr + ntp * (16 * BST * 2) + (192 + i32 + ks * 16) * 2);
#pragma unroll
                        for (int sub = 0; sub < 2; sub++) {
                            MMA(acc[0][2 * ntp + sub], a0, b[2 * sub], b[2 * sub + 1]);
                            MMA(acc[1][2 * ntp + sub], a1, b[2 * sub], b[2 * sub + 1]);
                        }
                    }
                }
            }
        }
        __syncthreads();   // mainloop done; B region free for scratch

        // prefetch A0/A1 for next tile (bufs 0,1 retired at chunks 9,10;
        // overlaps the whole epilogue). Harmless dummy on the last tile.
        issueA(0, 0);
        issueA(1, 1);

        if (t < 64) ssq[t] = 0.f;
        if (t >= 64 && t < 68) ss2[t - 64] = 0.f;
        __syncthreads();

        // ---- epilogue: per-position channel L2-norm ----
        {
            float cs[16];
#pragma unroll
            for (int nt = 0; nt < 8; nt++)
#pragma unroll
                for (int par = 0; par < 2; par++) {
                    float s = 0.f;
#pragma unroll
                    for (int mt = 0; mt < 2; mt++) {
                        float x0 = acc[mt][nt][par], x1 = acc[mt][nt][2 + par];
                        s = fmaf(x0, x0, s);
                        s = fmaf(x1, x1, s);
                    }
                    cs[nt * 2 + par] = s;
                }
#pragma unroll
            for (int i = 0; i < 16; i++) {
                cs[i] += __shfl_xor_sync(0xffffffffu, cs[i], 4);
                cs[i] += __shfl_xor_sync(0xffffffffu, cs[i], 8);
                cs[i] += __shfl_xor_sync(0xffffffffu, cs[i], 16);
            }
            if (lane < 4) {
#pragma unroll
                for (int nt = 0; nt < 8; nt++)
#pragma unroll
                    for (int par = 0; par < 2; par++)
                        atomicAdd(&ssq[nt * 8 + lane * 2 + par], cs[nt * 2 + par]);
            }
        }
        __syncthreads();
        if (t < 64) ssq[t] = 1.f / fmaxf(sqrtf(ssq[t]), 1e-12f);
        __syncthreads();

        // ---- pool over positions + final channel L2-norm ----
        float sq[4] = {0.f, 0.f, 0.f, 0.f};
#pragma unroll
        for (int mt = 0; mt < 2; mt++)
#pragma unroll
            for (int h = 0; h < 2; h++)
#pragma unroll
                for (int j = 0; j < 4; j++) {
                    float s = 0.f;
#pragma unroll
                    for (int ntl = 0; ntl < 2; ntl++) {
                        int nt = 2 * j + ntl;
#pragma unroll
                        for (int par = 0; par < 2; par++) {
                            int col = nt * 8 + (lane & 3) * 2 + par;
                            s = fmaf(acc[mt][nt][h * 2 + par], ssq[col], s);
                        }
                    }
                    s += __shfl_xor_sync(0xffffffffu, s, 1);
                    s += __shfl_xor_sync(0xffffffffu, s, 2);
                    if ((lane & 3) == 0) {
                        int row = w * 32 + mt * 16 + h * 8 + (lane >> 2);
                        float v = s * 0.0625f;
                        vsm[row * 4 + j] = v;
                        sq[j] = fmaf(v, v, sq[j]);
                    }
                }
#pragma unroll
        for (int j = 0; j < 4; j++) {
            sq[j] += __shfl_xor_sync(0xffffffffu, sq[j], 4);
            sq[j] += __shfl_xor_sync(0xffffffffu, sq[j], 8);
            sq[j] += __shfl_xor_sync(0xffffffffu, sq[j], 16);
        }
        if (lane == 0)
#pragma unroll
            for (int j = 0; j < 4; j++) atomicAdd(&ss2[j], sq[j]);
        __syncthreads();
        if (t < 4) ss2[t] = 1.f / fmaxf(sqrtf(ss2[t]), 1e-12f);
        __syncthreads();

        for (int g = t; g < 2560; g += 640) {
            int ch = g >> 2, j = g & 3;
            g_u[(size_t)(4 * jj + j) * CO + ch] = vsm[ch * 4 + j] * ss2[j];
        }
        __syncthreads();   // scratch reads done before next tile's B scatter
    }
}

// ---------------------------------------------------------------------------
// Sim + greedy: 2 queries per block (R14/R15, passing). 768 threads.
// ---------------------------------------------------------------------------
#define QS 644
#define JBLK 38
#define SIMSMT ((63 * QS + 720 * 9 + 810) * 4)   // 191448

__global__ void __launch_bounds__(768) k_sim(float* __restrict__ out) {
    extern __shared__ float smf[];
    float* rows = smf;                    // [63][QS]: 0-8 q0, 9-17 q1, 18-62 sup
    float* psum = smf + 63 * QS;          // [720][9]
    float* simm = psum + 720 * 9;         // [2][5][81]

    const int b = blockIdx.x / JBLK;
    const int j = blockIdx.x % JBLK;
    const int n0 = 2 * j;
    const int nq = (n0 + 1 < NQ_) ? 2 : 1;
    const int t = threadIdx.x;

    const float* q0b = g_u + ((size_t)(b * 80 + WAY_ + n0) * P_) * CO;
    const float* q1b = (nq == 2) ? q0b + (size_t)P_ * CO : q0b;
    const float* sb  = g_u + ((size_t)(b * 80) * P_) * CO;
    for (int i = t; i < 63 * 160; i += 768) {
        int r = i / 160, c4 = (i % 160) * 4;
        const float* src;
        if (r < 9)       src = q0b + (size_t)r * CO + c4;
        else if (r < 18) src = q1b + (size_t)(r - 9) * CO + c4;
        else             src = sb + (size_t)(r - 18) * CO + c4;
        *reinterpret_cast<float4*>(&rows[r * QS + c4]) =
            *reinterpret_cast<const float4*>(src);
    }
    __syncthreads();

    if (t < 720) {
        const int q = t / 360, r = t % 360;
        const int m = r / 72, rr = r % 72;
        const int tt = rr >> 3, ss = rr & 7;
        const int k0 = ss * 80;
        const float* s0 = &rows[(18 + m * 9 + (tt / 3) * 3 + 0) * QS + k0];
        const float* s1 = s0 + QS;
        const float* s2 = s1 + QS;
        const float* qq0 = &rows[(q * 9 + (tt % 3) * 3 + 0) * QS + k0];
        const float* qq1 = qq0 + QS;
        const float* qq2 = qq1 + QS;
        float a00 = 0.f, a01 = 0.f, a02 = 0.f;
        float a10 = 0.f, a11 = 0.f, a12 = 0.f;
        float a20 = 0.f, a21 = 0.f, a22 = 0.f;
#pragma unroll 2
        for (int k = 0; k < 80; k += 4) {
            float4 sv0 = *reinterpret_cast<const float4*>(s0 + k);
            float4 sv1 = *reinterpret_cast<const float4*>(s1 + k);
            float4 sv2 = *reinterpret_cast<const float4*>(s2 + k);
            float4 qv0 = *reinterpret_cast<const float4*>(qq0 + k);
            float4 qv1 = *reinterpret_cast<const float4*>(qq1 + k);
            float4 qv2 = *reinterpret_cast<const float4*>(qq2 + k);
            a00 = fmaf(sv0.x, qv0.x, a00); a00 = fmaf(sv0.y, qv0.y, a00);
            a00 = fmaf(sv0.z, qv0.z, a00); a00 = fmaf(sv0.w, qv0.w, a00);
            a01 = fmaf(sv0.x, qv1.x, a01); a01 = fmaf(sv0.y, qv1.y, a01);
            a01 = fmaf(sv0.z, qv1.z, a01); a01 = fmaf(sv0.w, qv1.w, a01);
            a02 = fmaf(sv0.x, qv2.x, a02); a02 = fmaf(sv0.y, qv2.y, a02);
            a02 = fmaf(sv0.z, qv2.z, a02); a02 = fmaf(sv0.w, qv2.w, a02);
            a10 = fmaf(sv1.x, qv0.x, a10); a10 = fmaf(sv1.y, qv0.y, a10);
            a10 = fmaf(sv1.z, qv0.z, a10); a10 = fmaf(sv1.w, qv0.w, a10);
            a11 = fmaf(sv1.x, qv1.x, a11); a11 = fmaf(sv1.y, qv1.y, a11);
            a11 = fmaf(sv1.z, qv1.z, a11); a11 = fmaf(sv1.w, qv1.w, a11);
            a12 = fmaf(sv1.x, qv2.x, a12); a12 = fmaf(sv1.y, qv2.y, a12);
            a12 = fmaf(sv1.z, qv2.z, a12); a12 = fmaf(sv1.w, qv2.w, a12);
            a20 = fmaf(sv2.x, qv0.x, a20); a20 = fmaf(sv2.y, qv0.y, a20);
            a20 = fmaf(sv2.z, qv0.z, a20); a20 = fmaf(sv2.w, qv0.w, a20);
            a21 = fmaf(sv2.x, qv1.x, a21); a21 = fmaf(sv2.y, qv1.y, a21);
            a21 = fmaf(sv2.z, qv1.z, a21); a21 = fmaf(sv2.w, qv1.w, a21);
            a22 = fmaf(sv2.x, qv2.x, a22); a22 = fmaf(sv2.y, qv2.y, a22);
            a22 = fmaf(sv2.z, qv2.z, a22); a22 = fmaf(sv2.w, qv2.w, a22);
        }
        float* pr = &psum[t * 9];
        pr[0] = a00; pr[1] = a01; pr[2] = a02;
        pr[3] = a10; pr[4] = a11; pr[5] = a12;
        pr[6] = a20; pr[7] = a21; pr[8] = a22;
    }
    __syncthreads();

    for (int i = t; i < 810; i += 768) {
        int q = i / 405, rem = i % 405;
        int m = rem / 81, e = rem % 81;
        int h = e / 9, wq = e % 9;
        int tile = (h / 3) * 3 + wq / 3;
        int el = (h % 3) * 3 + (wq % 3);
        float s = 0.f;
#pragma unroll
        for (int ss = 0; ss < 8; ss++)
            s += psum[(q * 360 + m * 72 + tile * 8 + ss) * 9 + el];
        simm[i] = s;
    }
    __syncthreads();

    const int wp = t >> 5, lane = t & 31;
    if (wp < 2 * WAY_) {
        const int q = wp / WAY_, m = wp % WAY_;
        if (q < nq) {
            const float* sv = &simm[(q * WAY_ + m) * 81];
            float v0 = sv[lane];
            float v1 = sv[lane + 32];
            float v2 = (lane + 64 < 81) ? sv[lane + 64] : -1e30f;
            unsigned rmask = 0x1FFu, cmask = 0x1FFu;
            float totalv = 0.f, beta = 1.f;
            for (int it = 0; it < 9; it++) {
                float bv = -1e30f;
                int bidx = 999;
                int jj = lane;
                if (((rmask >> (jj / 9)) & 1) && ((cmask >> (jj % 9)) & 1)) {
                    bv = v0; bidx = jj;
                }
                jj = lane + 32;
                if (((rmask >> (jj / 9)) & 1) && ((cmask >> (jj % 9)) & 1)) {
                    if (v1 > bv || (v1 == bv && jj < bidx)) { bv = v1; bidx = jj; }
                }
                jj = lane + 64;
                if (jj < 81 && ((rmask >> (jj / 9)) & 1) && ((cmask >> (jj % 9)) & 1)) {
                    if (v2 > bv || (v2 == bv && jj < bidx)) { bv = v2; bidx = jj; }
                }
#pragma unroll
                for (int off = 16; off; off >>= 1) {
                    float ov = __shfl_xor_sync(0xffffffffu, bv, off);
                    int   oi = __shfl_xor_sync(0xffffffffu, bidx, off);
                    if (ov > bv || (ov == bv && oi < bidx)) { bv = ov; bidx = oi; }
                }
                totalv = fmaf(fmaxf(bv, 0.f), beta, totalv);
                beta *= 0.5f;
                rmask &= ~(1u << (bidx / 9));
                cmask &= ~(1u << (bidx % 9));
            }
            if (lane == 0)
                out[((size_t)b * NQ_ + n0 + q) * WAY_ + m] = totalv;
        }
    }
}

// ---------------------------------------------------------------------------
extern "C" void kernel_launch(void* const* d_in, const int* in_sizes, int n_in,
                              void* d_out, int out_size) {
    const float* data   = (const float*)d_in[0];
    const float* conv_w = (const float*)d_in[1];
    (void)in_sizes; (void)n_in; (void)out_size;

    static bool attr_set = false;
    if (!attr_set) {
        cudaFuncSetAttribute(k_gemm, cudaFuncAttributeMaxDynamicSharedMemorySize, SMT);
        cudaFuncSetAttribute(k_sim, cudaFuncAttributeMaxDynamicSharedMemorySize, SIMSMT);
        attr_set = true;
    }

    k_prepw<<<(CO * KD + 255) / 256, 256>>>(conv_w);
    k_gemm<<<GRID_G, 640, SMT>>>(data);
    k_sim<<<B_ * JBLK, 768, SIMSMT>>>((float*)d_out);
}